// round 12
// baseline (speedup 1.0000x reference)
#include <cuda_runtime.h>
#include <cuda_bf16.h>

#define NT      320
#define FEAT    144
#define YDIM    25
#define EDGE_R  4864
#define NPATH   19

// Per-path tables (enumeration order = reference loops)
__constant__ int c_lo[NPATH]    = {0,0,0,1,1,1,1,1,1,1,2,2,2,2,2,2,2,2,2};
__constant__ int c_li[NPATH]    = {0,1,2,0,1,1,1,2,2,2,0,1,1,1,2,2,2,2,2};
__constant__ int c_lf[NPATH]    = {0,1,2,1,0,1,2,1,2,3,2,1,2,3,0,1,2,3,4};
__constant__ int c_cgoff[NPATH] = {0,1,10,35,44,53,80,125,170,245,350,375,420,495,600,625,700,825,1000};
__constant__ int c_cyoff[NPATH] = {0,1,4,9,12,21,30,39,54,69,84,89,104,119,134,159,184,209,234};
__constant__ int c_cyrow[NPATH] = {0,1,2,3,6,9,12,15,18,21,24,29,34,39,44,49,54,59,64};
__constant__ int c_b2off[NPATH] = {0,16,32,48,96,144,192,240,288,336,384,464,544,624,704,784,864,944,1024};
__constant__ int c_pair[NPATH]  = {0,1,2,3,4,4,4,5,5,5,6,7,7,7,8,8,8,8,8};
__constant__ int c_k[NPATH]     = {0,0,0,0,0,1,2,0,1,2,0,0,1,2,0,1,2,3,4};
__constant__ int c_gw[9]        = {0,20,40,60,120,276,432,532,792};
__constant__ int c_nlf9[9]      = {1,1,1,1,3,3,1,3,5};
// padded-F geometry per li: base word, v-stride
__constant__ int c_fpoff[3]     = {0,16,80};
__constant__ int c_fpstr[3]     = {1,4,8};

// Phase-C descriptor classes, LENGTH-SORTED (len4 x176, len12 x176, len20 x80).
// class order: pairs 0,1,2,3,6 (nlf1), 4,5,7 (nlf3), 8 (nlf5)
__constant__ int c_cls_base[9] = {0,16,32,48,96,176,224,272,352};
__constant__ int c_cls_rb[9]   = {0,80,160,240,736,320,528,816,1024};  // R f4 base
__constant__ int c_cls_gb[9]   = {0,5,10,15,108,30,69,133,198};        // G f4 base
__constant__ int c_cls_do[9]   = {1,1,1,3,5,3,3,5,5};
__constant__ int c_cls_nlf[9]  = {1,1,1,1,1,3,3,3,5};
__constant__ int c_cls_ob[9]   = {0,0,0,16,64,16,16,64,64};

// Precomputed tables (static device memory)
__device__ unsigned int   g_b1p[259];    // dst<<20 | wcgb<<9 | yb<<4 | df
__device__ unsigned int   g_b2p[1104];   // gdst<<21 | cyb<<11 | fb<<3 | di
__device__ unsigned int   g_cdesc[432];  // rf4 | gf4<<11 | outi<<20 | nlf<<28
__device__ float          g_wcg[1225];   // cg * W[path]
__device__ unsigned short g_rmap[1216];  // src f4 -> padded smem f4

__device__ __forceinline__ void cp_async16(unsigned int smem_addr, const void* gptr) {
    asm volatile("cp.async.cg.shared.global [%0], [%1], 16;"
                 :: "r"(smem_addr), "l"(gptr));
}

// Padded R layout per (lo,li) pair: 16 u-rows of (4*nlf+1) float4 each.
// Word stride 16nlf+4 == 20 (mod 32) -> conflict-free across u rows.
__device__ int map_r(int G4) {
    if (G4 < 256) { int r = G4 >> 6, l = G4 & 63; return r * 80 + (l >> 2) * 5 + (l & 3); }
    else if (G4 < 448) { int l = G4 - 256, u = l / 12; return 320 + u * 13 + (l - u * 12); }
    else if (G4 < 640) { int l = G4 - 448, u = l / 12; return 528 + u * 13 + (l - u * 12); }
    else if (G4 < 704) { int l = G4 - 640; return 736 + (l >> 2) * 5 + (l & 3); }
    else if (G4 < 896) { int l = G4 - 704, u = l / 12; return 816 + u * 13 + (l - u * 12); }
    else { int l = G4 - 896, u = l / 20; return 1024 + u * 21 + (l - u * 20); }
}

// prep: zero output + build all tables, O(1)-ish per thread (no rank sorts)
__global__ void prep_kernel(float* out, int n,
                            const float* __restrict__ cg, const float* __restrict__ W) {
    int t = blockIdx.x * blockDim.x + threadIdx.x;
    if (t < n) out[t] = 0.f;
    if (t < 259) {
        int p = 0;
        for (int q = 1; q < NPATH; ++q) if (t >= c_cyoff[q]) p = q;
        int j = t - c_cyoff[p];
        int li = c_li[p], lf = c_lf[p];
        int di = 2 * li + 1, df = 2 * lf + 1;
        int o = j / di, i = j - o * di;
        unsigned dst = (unsigned)((c_cyrow[p] + o) * 8 + i);
        g_b1p[t] = (dst << 20) | ((unsigned)(c_cgoff[p] + j * df) << 9)
                 | ((unsigned)(lf * lf) << 4) | (unsigned)df;
    }
    if (t < 1104) {
        int p = 0;
        for (int q = 1; q < NPATH; ++q) if (t >= c_b2off[q]) p = q;
        int j = t - c_b2off[p];
        int lo = c_lo[p], li = c_li[p];
        int doo = 2 * lo + 1, di = 2 * li + 1;
        int v = j / doo, o = j - v * doo;
        int pr = c_pair[p], nlf = c_nlf9[pr];
        unsigned gdst = (unsigned)(c_gw[pr] + o * (16 * nlf + 4) + v * nlf + c_k[p]);
        unsigned cyb  = (unsigned)((c_cyrow[p] + o) * 8);
        unsigned fb   = (unsigned)(c_fpoff[li] + v * c_fpstr[li]);
        g_b2p[t] = (gdst << 21) | (cyb << 11) | (fb << 3) | (unsigned)di;
    }
    if (t < 432) {    // phase-C descriptor, already length-sorted by class layout
        int c = 0;
        for (int q = 1; q < 9; ++q) if (t >= c_cls_base[q]) c = q;
        int j   = t - c_cls_base[c];
        int dd  = c_cls_do[c];
        int u   = j / dd, o = j - u * dd;
        int nlf = c_cls_nlf[c], str = 4 * nlf + 1;
        unsigned rf4  = (unsigned)(c_cls_rb[c] + u * str);
        unsigned gf4  = (unsigned)(c_cls_gb[c] + o * str);
        unsigned outi = (unsigned)(c_cls_ob[c] + u * dd + o);
        g_cdesc[t] = rf4 | (gf4 << 11) | (outi << 20) | ((unsigned)nlf << 28);
    }
    if (t < 1225) {
        int p = 0;
        for (int q = 1; q < NPATH; ++q) if (t >= c_cgoff[q]) p = q;
        g_wcg[t] = cg[t] * W[p];
    }
    if (t < 1216) g_rmap[t] = (unsigned short)map_r(t);
}

__global__ void __launch_bounds__(NT, 6)
tp_kernel(const float* __restrict__ feat, const float* __restrict__ rbf,
          const float* __restrict__ Y,    const int* __restrict__ aidx,
          const int* __restrict__ bidx,   float* __restrict__ out, int E)
{
    __shared__ float4 sR4[1360];     // padded R (21.8 KB)
    __shared__ float4 sG4[304];      // padded/interleaved W*G''
    __shared__ float4 sCY4[138];     // padded CY: 69 rows x 8 words
    __shared__ float4 sFp4[52];      // padded F: 208 words (li strides 1/4/8)
    __shared__ float  sY[32];

    float* sCY = reinterpret_cast<float*>(sCY4);
    float* sFp = reinterpret_cast<float*>(sFp4);

    const int e = blockIdx.x, tid = threadIdx.x;
    const int a = aidx[e];
    const int b = bidx[e];

    // ---- Phase A0: fire ALL R copies async (DRAM latency overlaps B1/B2) ----
    {
        const float4* r4 = reinterpret_cast<const float4*>(rbf + (size_t)e * EDGE_R);
        const unsigned int sR_base = (unsigned int)__cvta_generic_to_shared(sR4);
        #pragma unroll
        for (int i = 0; i < 4; ++i) {
            int t = tid + i * NT;
            if (t < 1216)
                cp_async16(sR_base + (unsigned)__ldg(&g_rmap[t]) * 16u, r4 + t);
        }
        asm volatile("cp.async.commit_group;");
    }

    // ---- Phase A1: F gather into PADDED layout + Y ----
    {
        const float* Fr = feat + (size_t)b * FEAT;
        if (tid < 208) {
            int w = tid;
            float val = 0.f;
            bool wr = true;
            if (w < 16) {
                val = __ldg(&Fr[w]);
            } else if (w < 80) {
                int v = (w - 16) >> 2, i = (w - 16) & 3;
                if (i < 3) val = __ldg(&Fr[16 + v * 3 + i]); else wr = false;
            } else {
                int v = (w - 80) >> 3, i = (w - 80) & 7;
                if (i < 5) val = __ldg(&Fr[64 + v * 5 + i]); else wr = false;
            }
            if (wr) sFp[w] = val;
        }
        if (tid >= 224 && tid < 224 + YDIM)
            sY[tid - 224] = __ldg(&Y[(size_t)e * YDIM + (tid - 224)]);
    }
    __syncthreads();

    // ---- Phase B1: CY[dst] = sum_f wcg[wb+f] * Y[yb+f]  (padded rows) ----
    if (tid < 259) {
        unsigned d = __ldg(&g_b1p[tid]);
        int df = d & 15, yb = (d >> 4) & 31, wb = (d >> 9) & 0x7FF, dst = d >> 20;
        float s = 0.f;
        for (int f = 0; f < df; ++f)
            s = fmaf(__ldg(&g_wcg[wb + f]), sY[yb + f], s);
        sCY[dst] = s;
    }
    __syncthreads();

    // ---- Phase B2: G''[gdst] = CY_row . F_row (vectorized LDS.128) ----
    float* sG = reinterpret_cast<float*>(sG4);
    for (int t = tid; t < 1104; t += NT) {
        unsigned d = __ldg(&g_b2p[t]);
        int di = d & 7, fb = (d >> 3) & 255, cyb = (d >> 11) & 1023, gdst = d >> 21;
        float s;
        if (di == 1) {
            s = sCY[cyb] * sFp[fb];
        } else {
            float4 cy = *reinterpret_cast<const float4*>(&sCY[cyb]);
            float4 fv = *reinterpret_cast<const float4*>(&sFp[fb]);
            s = cy.x * fv.x + cy.y * fv.y + cy.z * fv.z;
            if (di == 5)
                s += cy.w * fv.w + sCY[cyb + 4] * sFp[fb + 4];
        }
        sG[gdst] = s;
    }

    // R copies must have landed (and G'' visible) before phase C
    asm volatile("cp.async.wait_group 0;");
    __syncthreads();

    // ---- Phase C: length-sorted descriptor table — uniform warps, no div/mod ----
    float* outa = out + (size_t)a * FEAT;
    for (int t = tid; t < 432; t += NT) {
        unsigned d = __ldg(&g_cdesc[t]);
        const float4* r = sR4 + (d & 2047);
        const float4* g = sG4 + ((d >> 11) & 511);
        int outi = (d >> 20) & 255;
        int n4   = (int)(d >> 28) * 4;       // 4, 12 or 20 float4 pairs
        float a0 = 0.f, a1 = 0.f, a2 = 0.f, a3 = 0.f;
        for (int j = 0; j < n4; ++j) {
            float4 A = r[j];
            float4 B = g[j];
            a0 = fmaf(A.x, B.x, a0);
            a1 = fmaf(A.y, B.y, a1);
            a2 = fmaf(A.z, B.z, a2);
            a3 = fmaf(A.w, B.w, a3);
        }
        atomicAdd(outa + outi, (a0 + a1) + (a2 + a3));
    }
}

extern "C" void kernel_launch(void* const* d_in, const int* in_sizes, int n_in,
                              void* d_out, int out_size)
{
    const float* feat = (const float*)d_in[0];
    const float* rbf  = (const float*)d_in[1];
    const float* Y    = (const float*)d_in[2];
    const float* cg   = (const float*)d_in[3];
    const float* W    = (const float*)d_in[4];
    const int*   a    = (const int*)d_in[5];
    const int*   b    = (const int*)d_in[6];
    float* out = (float*)d_out;

    const int E = in_sizes[1] / EDGE_R;

    prep_kernel<<<(out_size + 255) / 256, 256>>>(out, out_size, cg, W);
    tp_kernel<<<E, NT>>>(feat, rbf, Y, a, b, out, E);
}

// round 13
// speedup vs baseline: 1.5743x; 1.5743x over previous
#include <cuda_runtime.h>
#include <cuda_bf16.h>

#define NT      288
#define FEAT    144
#define YDIM    25
#define EDGE_R  4864
#define NPATH   19

// Per-path tables (enumeration order = reference loops)
__constant__ int c_lo[NPATH]    = {0,0,0,1,1,1,1,1,1,1,2,2,2,2,2,2,2,2,2};
__constant__ int c_li[NPATH]    = {0,1,2,0,1,1,1,2,2,2,0,1,1,1,2,2,2,2,2};
__constant__ int c_lf[NPATH]    = {0,1,2,1,0,1,2,1,2,3,2,1,2,3,0,1,2,3,4};
__constant__ int c_cgoff[NPATH] = {0,1,10,35,44,53,80,125,170,245,350,375,420,495,600,625,700,825,1000};
__constant__ int c_cyoff[NPATH] = {0,1,4,9,12,21,30,39,54,69,84,89,104,119,134,159,184,209,234};
__constant__ int c_cyrow[NPATH] = {0,1,2,3,6,9,12,15,18,21,24,29,34,39,44,49,54,59,64};
__constant__ int c_b2off[NPATH] = {0,16,32,48,96,144,192,240,288,336,384,464,544,624,704,784,864,944,1024};
__constant__ int c_pair[NPATH]  = {0,1,2,3,4,4,4,5,5,5,6,7,7,7,8,8,8,8,8};
__constant__ int c_k[NPATH]     = {0,0,0,0,0,1,2,0,1,2,0,0,1,2,0,1,2,3,4};
__constant__ int c_gw[9]        = {0,20,40,60,120,276,432,532,792};
__constant__ int c_nlf9[9]      = {1,1,1,1,3,3,1,3,5};
// padded-F geometry per li: base word, v-stride
__constant__ int c_fpoff[3]     = {0,16,80};
__constant__ int c_fpstr[3]     = {1,4,8};

// Precomputed tables (static device memory)
__device__ unsigned int   g_b1p[259];    // dst<<20 | wb<<9 | stride<<3 | lf
__device__ unsigned int   g_b2p[1104];   // gdst<<21 | cyb<<11 | fb<<3 | di
__device__ float          g_wcgT[1225];  // TRANSPOSED: per path, df planes of (do*di)
__device__ unsigned short g_rmap[1216];  // src f4 -> padded smem f4

__device__ __forceinline__ void cp_async16(unsigned int smem_addr, const void* gptr) {
    asm volatile("cp.async.cg.shared.global [%0], [%1], 16;"
                 :: "r"(smem_addr), "l"(gptr));
}

// Padded R layout per (lo,li) pair: 16 u-rows of (4*nlf+1) float4 each.
// Word stride 16nlf+4 == 20 (mod 32) -> conflict-free across u rows.
__device__ int map_r(int G4) {
    if (G4 < 256) { int r = G4 >> 6, l = G4 & 63; return r * 80 + (l >> 2) * 5 + (l & 3); }
    else if (G4 < 448) { int l = G4 - 256, u = l / 12; return 320 + u * 13 + (l - u * 12); }
    else if (G4 < 640) { int l = G4 - 448, u = l / 12; return 528 + u * 13 + (l - u * 12); }
    else if (G4 < 704) { int l = G4 - 640; return 736 + (l >> 2) * 5 + (l & 3); }
    else if (G4 < 896) { int l = G4 - 704, u = l / 12; return 816 + u * 13 + (l - u * 12); }
    else { int l = G4 - 896, u = l / 20; return 1024 + u * 21 + (l - u * 20); }
}

// prep: zero output + build all tables (O(paths) per thread, no sorting)
__global__ void prep_kernel(float* out, int n,
                            const float* __restrict__ cg, const float* __restrict__ W) {
    int t = blockIdx.x * blockDim.x + threadIdx.x;
    if (t < n) out[t] = 0.f;
    if (t < 259) {
        int p = 0;
        for (int q = 1; q < NPATH; ++q) if (t >= c_cyoff[q]) p = q;
        int j = t - c_cyoff[p];
        int li = c_li[p], lf = c_lf[p], lo = c_lo[p];
        int di = 2 * li + 1, doo = 2 * lo + 1;
        int o = j / di, i = j - o * di;
        unsigned dst = (unsigned)((c_cyrow[p] + o) * 8 + i);
        unsigned str = (unsigned)(doo * di);
        g_b1p[t] = (dst << 20) | ((unsigned)(c_cgoff[p] + j) << 9)
                 | (str << 3) | (unsigned)lf;
    }
    if (t < 1104) {
        int p = 0;
        for (int q = 1; q < NPATH; ++q) if (t >= c_b2off[q]) p = q;
        int j = t - c_b2off[p];
        int lo = c_lo[p], li = c_li[p];
        int doo = 2 * lo + 1, di = 2 * li + 1;
        int v = j / doo, o = j - v * doo;
        int pr = c_pair[p], nlf = c_nlf9[pr];
        unsigned gdst = (unsigned)(c_gw[pr] + o * (16 * nlf + 4) + v * nlf + c_k[p]);
        unsigned cyb  = (unsigned)((c_cyrow[p] + o) * 8);
        unsigned fb   = (unsigned)(c_fpoff[li] + v * c_fpstr[li]);
        g_b2p[t] = (gdst << 21) | (cyb << 11) | (fb << 3) | (unsigned)di;
    }
    if (t < 1225) {   // transposed W-folded cg: wcgT[cgoff + f*(do*di) + j] = cg[cgoff + j*df + f]*W[p]
        int p = 0;
        for (int q = 1; q < NPATH; ++q) if (t >= c_cgoff[q]) p = q;
        int local = t - c_cgoff[p];
        int lo = c_lo[p], li = c_li[p], lf = c_lf[p];
        int n2 = (2 * lo + 1) * (2 * li + 1), df = 2 * lf + 1;
        int f = local / n2, j = local - f * n2;
        g_wcgT[t] = cg[c_cgoff[p] + j * df + f] * W[p];
    }
    if (t < 1216) g_rmap[t] = (unsigned short)map_r(t);
}

// acc += R_row . G_row over 4*NLF float4 from padded smem (conflict-free, broadcast-dedup)
template<int NLF>
__device__ __forceinline__ float pairdot_s(const float4* __restrict__ sR4,
                                           const float4* __restrict__ sG4,
                                           int rf4, int gf4, int u, int o) {
    const float4* r = sR4 + rf4 + u * (4 * NLF + 1);
    const float4* g = sG4 + gf4 + o * (4 * NLF + 1);
    float a0 = 0.f, a1 = 0.f, a2 = 0.f, a3 = 0.f;
    #pragma unroll
    for (int j = 0; j < 4 * NLF; ++j) {
        float4 A = r[j];
        float4 B = g[j];
        a0 = fmaf(A.x, B.x, a0);
        a1 = fmaf(A.y, B.y, a1);
        a2 = fmaf(A.z, B.z, a2);
        a3 = fmaf(A.w, B.w, a3);
    }
    return (a0 + a1) + (a2 + a3);
}

__global__ void __launch_bounds__(NT, 6)
tp_kernel(const float* __restrict__ feat, const float* __restrict__ rbf,
          const float* __restrict__ Y,    const int* __restrict__ aidx,
          const int* __restrict__ bidx,   float* __restrict__ out, int E)
{
    __shared__ float4 sR4[1360];     // padded R (21.8 KB)
    __shared__ float4 sG4[304];      // padded/interleaved W*G''
    __shared__ float4 sCY4[138];     // padded CY: 69 rows x 8 words
    __shared__ float4 sFp4[52];      // padded F: 208 words (li strides 1/4/8)
    __shared__ float  sY[32];

    float* sCY = reinterpret_cast<float*>(sCY4);
    float* sFp = reinterpret_cast<float*>(sFp4);

    const int e = blockIdx.x, tid = threadIdx.x;
    const int a = aidx[e];
    const int b = bidx[e];

    // ---- Phase A0: fire ALL R copies async (DRAM latency overlaps B1/B2) ----
    {
        const float4* r4 = reinterpret_cast<const float4*>(rbf + (size_t)e * EDGE_R);
        const unsigned int sR_base = (unsigned int)__cvta_generic_to_shared(sR4);
        #pragma unroll
        for (int i = 0; i < 5; ++i) {
            int t = tid + i * NT;
            if (t < 1216)
                cp_async16(sR_base + (unsigned)__ldg(&g_rmap[t]) * 16u, r4 + t);
        }
        asm volatile("cp.async.commit_group;");
    }

    // ---- Phase A1: F gather into PADDED layout + Y ----
    {
        const float* Fr = feat + (size_t)b * FEAT;
        if (tid < 208) {
            int w = tid;
            float val = 0.f;
            bool wr = true;
            if (w < 16) {
                val = __ldg(&Fr[w]);
            } else if (w < 80) {
                int v = (w - 16) >> 2, i = (w - 16) & 3;
                if (i < 3) val = __ldg(&Fr[16 + v * 3 + i]); else wr = false;
            } else {
                int v = (w - 80) >> 3, i = (w - 80) & 7;
                if (i < 5) val = __ldg(&Fr[64 + v * 5 + i]); else wr = false;
            }
            if (wr) sFp[w] = val;
        }
        if (tid >= 224 && tid < 224 + YDIM)
            sY[tid - 224] = __ldg(&Y[(size_t)e * YDIM + (tid - 224)]);
    }
    __syncthreads();

    // ---- Phase B1: CY[dst] = sum_f wcgT[wb + f*str] * Y[lf*lf+f]  (coalesced lanes) ----
    if (tid < 259) {
        unsigned d = __ldg(&g_b1p[tid]);
        int lf = d & 7, str = (d >> 3) & 63, wb = (d >> 9) & 0x7FF, dst = d >> 20;
        int df = 2 * lf + 1, yb = lf * lf;
        float s = 0.f;
        for (int f = 0; f < df; ++f)
            s = fmaf(__ldg(&g_wcgT[wb + f * str]), sY[yb + f], s);
        sCY[dst] = s;
    }
    __syncthreads();

    // ---- Phase B2: G''[gdst] = CY_row . F_row (vectorized LDS.128) ----
    float* sG = reinterpret_cast<float*>(sG4);
    for (int t = tid; t < 1104; t += NT) {
        unsigned d = __ldg(&g_b2p[t]);
        int di = d & 7, fb = (d >> 3) & 255, cyb = (d >> 11) & 1023, gdst = d >> 21;
        float s;
        if (di == 1) {
            s = sCY[cyb] * sFp[fb];
        } else {
            float4 cy = *reinterpret_cast<const float4*>(&sCY[cyb]);
            float4 fv = *reinterpret_cast<const float4*>(&sFp[fb]);
            s = cy.x * fv.x + cy.y * fv.y + cy.z * fv.z;
            if (di == 5)
                s += cy.w * fv.w + sCY[cyb + 4] * sFp[fb + 4];
        }
        sG[gdst] = s;
    }

    // R copies must have landed (and G'' visible) before phase C
    asm volatile("cp.async.wait_group 0;");
    __syncthreads();

    // ---- Phase C: balanced split — two threads per lo=1/lo=2 output ----
    if (tid < 272) {
        float acc;
        int outi;
        if (tid < 16) {                          // lo=0 (48 FMA)
            const int u = tid;
            acc  = pairdot_s<1>(sR4, sG4,    0,   0, u, 0);
            acc += pairdot_s<1>(sR4, sG4,   80,   5, u, 0);
            acc += pairdot_s<1>(sR4, sG4,  160,  10, u, 0);
            outi = u;
        } else if (tid < 64) {                   // lo=1 h0 (64 FMA)
            const int s = tid - 16, u = s / 3, o = s - u * 3;
            acc  = pairdot_s<1>(sR4, sG4,  240,  15, u, o);
            acc += pairdot_s<3>(sR4, sG4,  320,  30, u, o);
            outi = 16 + u * 3 + o;
        } else if (tid < 112) {                  // lo=1 h1 (48 FMA)
            const int s = tid - 64, u = s / 3, o = s - u * 3;
            acc  = pairdot_s<3>(sR4, sG4,  528,  69, u, o);
            outi = 16 + u * 3 + o;
        } else if (tid < 192) {                  // lo=2 h0 (64 FMA)
            const int s = tid - 112, u = s / 5, o = s - u * 5;
            acc  = pairdot_s<1>(sR4, sG4,  736, 108, u, o);
            acc += pairdot_s<3>(sR4, sG4,  816, 133, u, o);
            outi = 64 + u * 5 + o;
        } else {                                 // lo=2 h1 (80 FMA)
            const int s = tid - 192, u = s / 5, o = s - u * 5;
            acc  = pairdot_s<5>(sR4, sG4, 1024, 198, u, o);
            outi = 64 + u * 5 + o;
        }
        atomicAdd(out + (size_t)a * FEAT + outi, acc);
    }
}

extern "C" void kernel_launch(void* const* d_in, const int* in_sizes, int n_in,
                              void* d_out, int out_size)
{
    const float* feat = (const float*)d_in[0];
    const float* rbf  = (const float*)d_in[1];
    const float* Y    = (const float*)d_in[2];
    const float* cg   = (const float*)d_in[3];
    const float* W    = (const float*)d_in[4];
    const int*   a    = (const int*)d_in[5];
    const int*   b    = (const int*)d_in[6];
    float* out = (float*)d_out;

    const int E = in_sizes[1] / EDGE_R;

    prep_kernel<<<(out_size + 255) / 256, 256>>>(out, out_size, cg, W);
    tp_kernel<<<E, NT>>>(feat, rbf, Y, a, b, out, E);
}

// round 14
// speedup vs baseline: 1.5965x; 1.0141x over previous
#include <cuda_runtime.h>
#include <cuda_bf16.h>

#define NT      288
#define FEAT    144
#define YDIM    25
#define EDGE_R  4864
#define NPATH   19

// Per-path tables (enumeration order = reference loops)
__constant__ int c_lo[NPATH]    = {0,0,0,1,1,1,1,1,1,1,2,2,2,2,2,2,2,2,2};
__constant__ int c_li[NPATH]    = {0,1,2,0,1,1,1,2,2,2,0,1,1,1,2,2,2,2,2};
__constant__ int c_lf[NPATH]    = {0,1,2,1,0,1,2,1,2,3,2,1,2,3,0,1,2,3,4};
__constant__ int c_cgoff[NPATH] = {0,1,10,35,44,53,80,125,170,245,350,375,420,495,600,625,700,825,1000};
__constant__ int c_cyoff[NPATH] = {0,1,4,9,12,21,30,39,54,69,84,89,104,119,134,159,184,209,234};
__constant__ int c_cyrow[NPATH] = {0,1,2,3,6,9,12,15,18,21,24,29,34,39,44,49,54,59,64};
__constant__ int c_b2off[NPATH] = {0,16,32,48,96,144,192,240,288,336,384,464,544,624,704,784,864,944,1024};
__constant__ int c_pair[NPATH]  = {0,1,2,3,4,4,4,5,5,5,6,7,7,7,8,8,8,8,8};
__constant__ int c_k[NPATH]     = {0,0,0,0,0,1,2,0,1,2,0,0,1,2,0,1,2,3,4};
__constant__ int c_gw[9]        = {0,20,40,60,120,276,432,532,792};
__constant__ int c_nlf9[9]      = {1,1,1,1,3,3,1,3,5};
// padded-F geometry per li: base word, v-stride
__constant__ int c_fpoff[3]     = {0,16,80};
__constant__ int c_fpstr[3]     = {1,4,8};
// df-sorted B1 placement: rank = c_b1rank[p] + j  (sorted by lf asc, path asc)
__constant__ int c_b1rank[NPATH] = {0,35,105,38,1,41,110,50,119,179,134,65,139,194,10,80,154,209,234};

// Precomputed tables (static device memory)
__device__ unsigned int   g_b1p[259];    // dst<<20 | wb<<9 | stride<<3 | lf   (df-sorted order)
__device__ unsigned int   g_b2p[1104];   // gdst<<21 | cyb<<11 | fb<<3 | di
__device__ float          g_wcgT[1225];  // TRANSPOSED: per path, df planes of (do*di)
__device__ unsigned short g_rmap[1216];  // src f4 -> padded smem f4

__device__ __forceinline__ void cp_async16(unsigned int smem_addr, const void* gptr) {
    asm volatile("cp.async.cg.shared.global [%0], [%1], 16;"
                 :: "r"(smem_addr), "l"(gptr));
}

// Padded R layout per (lo,li) pair: 16 u-rows of (4*nlf+1) float4 each.
// Word stride 16nlf+4 == 20 (mod 32) -> conflict-free across u rows.
__device__ int map_r(int G4) {
    if (G4 < 256) { int r = G4 >> 6, l = G4 & 63; return r * 80 + (l >> 2) * 5 + (l & 3); }
    else if (G4 < 448) { int l = G4 - 256, u = l / 12; return 320 + u * 13 + (l - u * 12); }
    else if (G4 < 640) { int l = G4 - 448, u = l / 12; return 528 + u * 13 + (l - u * 12); }
    else if (G4 < 704) { int l = G4 - 640; return 736 + (l >> 2) * 5 + (l & 3); }
    else if (G4 < 896) { int l = G4 - 704, u = l / 12; return 816 + u * 13 + (l - u * 12); }
    else { int l = G4 - 896, u = l / 20; return 1024 + u * 21 + (l - u * 20); }
}

// prep: zero output + build all tables (O(paths) per thread, no sorting loops)
__global__ void prep_kernel(float* out, int n,
                            const float* __restrict__ cg, const float* __restrict__ W) {
    int t = blockIdx.x * blockDim.x + threadIdx.x;
    if (t < n) out[t] = 0.f;
    if (t < 259) {
        int p = 0;
        for (int q = 1; q < NPATH; ++q) if (t >= c_cyoff[q]) p = q;
        int j = t - c_cyoff[p];
        int li = c_li[p], lf = c_lf[p], lo = c_lo[p];
        int di = 2 * li + 1, doo = 2 * lo + 1;
        int o = j / di, i = j - o * di;
        unsigned dst = (unsigned)((c_cyrow[p] + o) * 8 + i);
        unsigned str = (unsigned)(doo * di);
        unsigned desc = (dst << 20) | ((unsigned)(c_cgoff[p] + j) << 9)
                      | (str << 3) | (unsigned)lf;
        g_b1p[c_b1rank[p] + j] = desc;      // df-sorted placement, O(1)
    }
    if (t < 1104) {
        int p = 0;
        for (int q = 1; q < NPATH; ++q) if (t >= c_b2off[q]) p = q;
        int j = t - c_b2off[p];
        int lo = c_lo[p], li = c_li[p];
        int doo = 2 * lo + 1, di = 2 * li + 1;
        int v = j / doo, o = j - v * doo;
        int pr = c_pair[p], nlf = c_nlf9[pr];
        unsigned gdst = (unsigned)(c_gw[pr] + o * (16 * nlf + 4) + v * nlf + c_k[p]);
        unsigned cyb  = (unsigned)((c_cyrow[p] + o) * 8);
        unsigned fb   = (unsigned)(c_fpoff[li] + v * c_fpstr[li]);
        g_b2p[t] = (gdst << 21) | (cyb << 11) | (fb << 3) | (unsigned)di;
    }
    if (t < 1225) {   // transposed W-folded cg
        int p = 0;
        for (int q = 1; q < NPATH; ++q) if (t >= c_cgoff[q]) p = q;
        int local = t - c_cgoff[p];
        int lo = c_lo[p], li = c_li[p], lf = c_lf[p];
        int n2 = (2 * lo + 1) * (2 * li + 1), df = 2 * lf + 1;
        int f = local / n2, j = local - f * n2;
        g_wcgT[t] = cg[c_cgoff[p] + j * df + f] * W[p];
    }
    if (t < 1216) g_rmap[t] = (unsigned short)map_r(t);
}

// acc += R_row . G_row over 4*NLF float4 from padded smem (conflict-free, broadcast-dedup)
template<int NLF>
__device__ __forceinline__ float pairdot_s(const float4* __restrict__ sR4,
                                           const float4* __restrict__ sG4,
                                           int rf4, int gf4, int u, int o) {
    const float4* r = sR4 + rf4 + u * (4 * NLF + 1);
    const float4* g = sG4 + gf4 + o * (4 * NLF + 1);
    float a0 = 0.f, a1 = 0.f, a2 = 0.f, a3 = 0.f;
    #pragma unroll
    for (int j = 0; j < 4 * NLF; ++j) {
        float4 A = r[j];
        float4 B = g[j];
        a0 = fmaf(A.x, B.x, a0);
        a1 = fmaf(A.y, B.y, a1);
        a2 = fmaf(A.z, B.z, a2);
        a3 = fmaf(A.w, B.w, a3);
    }
    return (a0 + a1) + (a2 + a3);
}

__global__ void __launch_bounds__(NT, 7)
tp_kernel(const float* __restrict__ feat, const float* __restrict__ rbf,
          const float* __restrict__ Y,    const int* __restrict__ aidx,
          const int* __restrict__ bidx,   float* __restrict__ out, int E)
{
    __shared__ float4 sR4[1360];     // padded R (21.8 KB)
    __shared__ float4 sG4[304];      // padded/interleaved W*G''
    __shared__ float4 sCY4[138];     // padded CY: 69 rows x 8 words
    __shared__ float4 sFp4[52];      // padded F: 208 words (li strides 1/4/8)
    __shared__ float  sY[32];

    float* sCY = reinterpret_cast<float*>(sCY4);
    float* sFp = reinterpret_cast<float*>(sFp4);

    const int e = blockIdx.x, tid = threadIdx.x;
    const int a = aidx[e];
    const int b = bidx[e];

    // ---- Phase A0: fire ALL R copies async (DRAM latency overlaps B1/B2) ----
    {
        const float4* r4 = reinterpret_cast<const float4*>(rbf + (size_t)e * EDGE_R);
        const unsigned int sR_base = (unsigned int)__cvta_generic_to_shared(sR4);
        #pragma unroll
        for (int i = 0; i < 5; ++i) {
            int t = tid + i * NT;
            if (t < 1216)
                cp_async16(sR_base + (unsigned)__ldg(&g_rmap[t]) * 16u, r4 + t);
        }
        asm volatile("cp.async.commit_group;");
    }

    // ---- Phase A1: F gather into PADDED layout + Y ----
    {
        const float* Fr = feat + (size_t)b * FEAT;
        if (tid < 208) {
            int w = tid;
            float val = 0.f;
            bool wr = true;
            if (w < 16) {
                val = __ldg(&Fr[w]);
            } else if (w < 80) {
                int v = (w - 16) >> 2, i = (w - 16) & 3;
                if (i < 3) val = __ldg(&Fr[16 + v * 3 + i]); else wr = false;
            } else {
                int v = (w - 80) >> 3, i = (w - 80) & 7;
                if (i < 5) val = __ldg(&Fr[64 + v * 5 + i]); else wr = false;
            }
            if (wr) sFp[w] = val;
        }
        if (tid >= 224 && tid < 224 + YDIM)
            sY[tid - 224] = __ldg(&Y[(size_t)e * YDIM + (tid - 224)]);
    }
    __syncthreads();

    // ---- Phase B1: CY[dst] = sum_f wcgT[wb + f*str] * Y[lf*lf+f]
    //      df-sorted order -> warps have uniform df, no max-df penalty ----
    if (tid < 259) {
        unsigned d = __ldg(&g_b1p[tid]);
        int lf = d & 7, str = (d >> 3) & 63, wb = (d >> 9) & 0x7FF, dst = d >> 20;
        int df = 2 * lf + 1, yb = lf * lf;
        float s = 0.f;
        for (int f = 0; f < df; ++f)
            s = fmaf(__ldg(&g_wcgT[wb + f * str]), sY[yb + f], s);
        sCY[dst] = s;
    }
    __syncthreads();

    // ---- Phase B2: G''[gdst] = CY_row . F_row (vectorized LDS.128) ----
    float* sG = reinterpret_cast<float*>(sG4);
    for (int t = tid; t < 1104; t += NT) {
        unsigned d = __ldg(&g_b2p[t]);
        int di = d & 7, fb = (d >> 3) & 255, cyb = (d >> 11) & 1023, gdst = d >> 21;
        float s;
        if (di == 1) {
            s = sCY[cyb] * sFp[fb];
        } else {
            float4 cy = *reinterpret_cast<const float4*>(&sCY[cyb]);
            float4 fv = *reinterpret_cast<const float4*>(&sFp[fb]);
            s = cy.x * fv.x + cy.y * fv.y + cy.z * fv.z;
            if (di == 5)
                s += cy.w * fv.w + sCY[cyb + 4] * sFp[fb + 4];
        }
        sG[gdst] = s;
    }

    // R copies must have landed (and G'' visible) before phase C
    asm volatile("cp.async.wait_group 0;");
    __syncthreads();

    // ---- Phase C: balanced split — two threads per lo=1/lo=2 output ----
    if (tid < 272) {
        float acc;
        int outi;
        if (tid < 16) {                          // lo=0 (48 FMA)
            const int u = tid;
            acc  = pairdot_s<1>(sR4, sG4,    0,   0, u, 0);
            acc += pairdot_s<1>(sR4, sG4,   80,   5, u, 0);
            acc += pairdot_s<1>(sR4, sG4,  160,  10, u, 0);
            outi = u;
        } else if (tid < 64) {                   // lo=1 h0 (64 FMA)
            const int s = tid - 16, u = s / 3, o = s - u * 3;
            acc  = pairdot_s<1>(sR4, sG4,  240,  15, u, o);
            acc += pairdot_s<3>(sR4, sG4,  320,  30, u, o);
            outi = 16 + u * 3 + o;
        } else if (tid < 112) {                  // lo=1 h1 (48 FMA)
            const int s = tid - 64, u = s / 3, o = s - u * 3;
            acc  = pairdot_s<3>(sR4, sG4,  528,  69, u, o);
            outi = 16 + u * 3 + o;
        } else if (tid < 192) {                  // lo=2 h0 (64 FMA)
            const int s = tid - 112, u = s / 5, o = s - u * 5;
            acc  = pairdot_s<1>(sR4, sG4,  736, 108, u, o);
            acc += pairdot_s<3>(sR4, sG4,  816, 133, u, o);
            outi = 64 + u * 5 + o;
        } else {                                 // lo=2 h1 (80 FMA)
            const int s = tid - 192, u = s / 5, o = s - u * 5;
            acc  = pairdot_s<5>(sR4, sG4, 1024, 198, u, o);
            outi = 64 + u * 5 + o;
        }
        atomicAdd(out + (size_t)a * FEAT + outi, acc);
    }
}

extern "C" void kernel_launch(void* const* d_in, const int* in_sizes, int n_in,
                              void* d_out, int out_size)
{
    const float* feat = (const float*)d_in[0];
    const float* rbf  = (const float*)d_in[1];
    const float* Y    = (const float*)d_in[2];
    const float* cg   = (const float*)d_in[3];
    const float* W    = (const float*)d_in[4];
    const int*   a    = (const int*)d_in[5];
    const int*   b    = (const int*)d_in[6];
    float* out = (float*)d_out;

    const int E = in_sizes[1] / EDGE_R;

    prep_kernel<<<(out_size + 255) / 256, 256>>>(out, out_size, cg, W);
    tp_kernel<<<E, NT>>>(feat, rbf, Y, a, b, out, E);
}